// round 16
// baseline (speedup 1.0000x reference)
#include <cuda_runtime.h>

// LSTM autoencoder: enc (F=32 -> H=64), dec (H=64 -> F=32), B=512, T=1024.
// 128 blocks x 384 threads, 4 batch rows/block.
// TWO-ROW PHASE PIPELINE: each step = 2 phases.
//   phase A(it): FMA rows{0,1}(it)  + reduce/ew rows{2,3}(it-1)
//   phase B(it): FMA rows{2,3}(it)  + reduce/ew rows{0,1}(it)
// The old phase's shfl/MUFU/store tail issues in the shadow of the new
// phase's 96 FFMA2s. tid = pg*8 + s: pg = unit-PAIR (0..31 enc, 32..47 dec),
// s = k-eighth lane. Weights packed gate-pairwise (two GATES at the same k
// per ull): c0/c1 = MY unit (IF)/(GO), c2/c3 = partner unit. hv is fed as
// duplicated scalars pk(F,F) from 3 x LDS.128 (12 floats) per slot — the
// R15 crash was an ulonglong2 hv rewrite that broke this layout and read
// 24 floats OOB. Per phase: 2 slots (slot l = row RB + ((s^l)&1)) x 4 chains
// = 96 ffma2. Reduction per chain: xor1 row-merge + xor2 + xor4 select-free
// unit exchange; lanes s / s^2 duplicate ew, stores predicated on lead.
// All activations tanh.approx (i,f,o pre-scaled 0.5); biases = 2 packed regs
// added post-reduction. XHP=104: slot bank bases 8*((s^l)&1)+12s distinct
// mod 32 -> conflict-free, 4-way-broadcast LDS.128.
// Double-buffered xh per step parity, decoder lags encoder by 1 step.

#define T_STEPS 1024
#define FDIM    32
#define HDIM    64
#define ROWS    4
#define NBLK    128
#define NTHR    384
#define XHP     104

#define OFF_XHE(b) ((b) * (ROWS * XHP))
#define OFF_XHD(b) (2 * ROWS * XHP + (b) * (ROWS * XHP))
#define SMEMN      (4 * ROWS * XHP)

typedef unsigned long long ull;
union U64F2 { ull u; float2 f; };

__device__ __forceinline__ ull pk(float lo, float hi) {
    U64F2 u; u.f = make_float2(lo, hi); return u.u;
}
__device__ __forceinline__ ull ffma2(ull a, ull b, ull c) {
    ull d;
    asm("fma.rn.f32x2 %0, %1, %2, %3;" : "=l"(d) : "l"(a), "l"(b), "l"(c));
    return d;
}
__device__ __forceinline__ ull padd2(ull a, ull b) {
    ull d;
    asm("add.rn.f32x2 %0, %1, %2;" : "=l"(d) : "l"(a), "l"(b));
    return d;
}
__device__ __forceinline__ ull shx64(ull v, int m) {
    return __shfl_xor_sync(0xFFFFFFFFu, v, m);
}
__device__ __forceinline__ float tanh_hw(float x) {
    float r; asm("tanh.approx.f32 %0, %1;" : "=f"(r) : "f"(x)); return r;
}
__device__ __forceinline__ float sig_hw(float g) {   // g pre-scaled by 0.5
    return fmaf(0.5f, tanh_hw(g), 0.5f);
}

__global__ void __launch_bounds__(NTHR, 1) lstm_ae_kernel(
    const float* __restrict__ x,
    const float* __restrict__ ew_ih, const float* __restrict__ ew_hh,
    const float* __restrict__ eb_ih, const float* __restrict__ eb_hh,
    const float* __restrict__ dw_ih, const float* __restrict__ dw_hh,
    const float* __restrict__ db_ih, const float* __restrict__ db_hh,
    float* __restrict__ out)
{
    __shared__ __align__(16) float sm[SMEMN];
    const int tid = threadIdx.x;
    const int b0  = blockIdx.x * ROWS;

    const int pg   = tid >> 3;            // unit-pair 0..47 (warp = 4 pairs)
    const bool dec = (pg >= 32);
    const int pp   = dec ? (pg - 32) : pg;
    const int s    = tid & 7;             // k-eighth lane
    const int uu   = (s >> 2) & 1;
    const int kb   = 12 * s;
    const int uA   = 2 * pp;
    const int U    = uA + uu;             // my unit -> chains c0/c1
    const int Uo   = uA + (uu ^ 1);       // partner unit -> chains c2/c3
    const bool lead = ((s >> 1) & 1) == 0;
    const int rlo  = s & 1;               // my low ew row (phase B)
    const int rhi  = 2 + rlo;             // my high ew row (phase A)

    // ---- weights: c0/c1 = MY unit (IF)/(GO), c2/c3 = partner; 0.5 on i,f,o ----
    ull w0[12], w1[12], w2[12], w3[12];
    {
        const int NU = dec ? FDIM : HDIM;
        const int KI = dec ? HDIM : FDIM;
        const int KH = dec ? FDIM : HDIM;
        const float* wih = dec ? dw_ih : ew_ih;
        const float* whh = dec ? dw_hh : ew_hh;
        #define WV(G, K) ((K) < KI ? wih[(G) * KI + (K)] : whh[(G) * KH + ((K) - KI)])
        #pragma unroll
        for (int j = 0; j < 12; ++j) {
            const int k = kb + j;
            w0[j] = pk(0.5f * WV(U, k),        0.5f * WV(U + NU, k));
            w1[j] = pk(WV(U + 2 * NU, k),      0.5f * WV(U + 3 * NU, k));
            w2[j] = pk(0.5f * WV(Uo, k),       0.5f * WV(Uo + NU, k));
            w3[j] = pk(WV(Uo + 2 * NU, k),     0.5f * WV(Uo + 3 * NU, k));
        }
        #undef WV
    }

    // ---- my unit's packed biases (added post-reduction) ----
    ull bIF, bGO;
    {
        const int NU = dec ? FDIM : HDIM;
        const float* bih = dec ? db_ih : eb_ih;
        const float* bhh = dec ? db_hh : eb_hh;
        #define BV(G) (bih[G] + bhh[G])
        bIF = pk(0.5f * BV(U),       0.5f * BV(U + NU));
        bGO = pk(BV(U + 2 * NU),     0.5f * BV(U + 3 * NU));
        #undef BV
    }

    // ---- init state; x(0); prime x(1) for both my rows (dec lead lanes) ----
    for (int i = tid; i < SMEMN; i += NTHR) sm[i] = 0.0f;
    __syncthreads();
    const float* xlo_base = x + ((size_t)(b0 + rlo) * T_STEPS) * FDIM + U;
    const float* xhi_base = x + ((size_t)(b0 + rhi) * T_STEPS) * FDIM + U;
    float* outp_lo = out + ((size_t)(b0 + rlo) * T_STEPS) * FDIM + U;
    float* outp_hi = out + ((size_t)(b0 + rhi) * T_STEPS) * FDIM + U;
    const float* xl_lo = xlo_base + 2 * FDIM;
    const float* xl_hi = xhi_base + 2 * FDIM;
    float x_lo = 0.0f, x_hi = 0.0f;
    if (dec && lead) {
        sm[OFF_XHE(0) + rlo * XHP + U] = xlo_base[0];
        sm[OFF_XHE(0) + rhi * XHP + U] = xhi_base[0];
        x_lo = xlo_base[FDIM];
        x_hi = xhi_base[FDIM];
    }
    __syncthreads();

    // slot row offsets within a row-pair
    const int roL0 = (s & 1) * XHP;
    const int roL1 = ((s ^ 1) & 1) * XHP;

    float c_lo = 0.0f, c_hi = 0.0f;

    // accumulator banks: pA/qA = bank A slots 0/1; pB/qB = bank B
    ull pA0, pA1, pA2, pA3, qA0, qA1, qA2, qA3;
    ull pB0, pB1, pB2, pB3, qB0, qB1, qB2, qB3;

    #define KS(J, F)                                                      \
    {                                                                     \
        ull hd = pk(F, F);                                                \
        c0 = ffma2(w0[J], hd, c0); c1 = ffma2(w1[J], hd, c1);             \
        c2 = ffma2(w2[J], hd, c2); c3 = ffma2(w3[J], hd, c3);             \
    }
    #define SLOT(XB, RO, O0, O1, O2, O3)                                  \
    {                                                                     \
        const float4* hp = reinterpret_cast<const float4*>((XB) + (RO));  \
        float4 v0 = hp[0], v1 = hp[1], v2 = hp[2];                        \
        ull c0 = 0ull, c1 = 0ull, c2 = 0ull, c3 = 0ull;                   \
        KS(0, v0.x) KS(1, v0.y) KS(2, v0.z) KS(3, v0.w)                   \
        KS(4, v1.x) KS(5, v1.y) KS(6, v1.z) KS(7, v1.w)                   \
        KS(8, v2.x) KS(9, v2.y) KS(10, v2.z) KS(11, v2.w)                 \
        O0 = c0; O1 = c1; O2 = c2; O3 = c3;                               \
    }
    #define FMA8(RBUF, RBOFF, P0,P1,P2,P3, Q0,Q1,Q2,Q3)                   \
    {                                                                     \
        const float* xb = sm + (dec ? OFF_XHD(RBUF) : OFF_XHE(RBUF))      \
                          + (RBOFF) + kb;                                 \
        SLOT(xb, roL0, P0, P1, P2, P3)                                    \
        SLOT(xb, roL1, Q0, Q1, Q2, Q3)                                    \
    }

    #define RED_EW(P0,P1,P2,P3, Q0,Q1,Q2,Q3, RBE, CST, ENCL, DECL, WBUF, \
                   OUTP, XPR, XLP, XWC, XLC)                              \
    {                                                                     \
        ull t0 = padd2(P0, shx64(Q0, 1));                                 \
        ull t2 = padd2(P2, shx64(Q2, 1));                                 \
        t0 = padd2(t0, shx64(t0, 2));                                     \
        t2 = padd2(t2, shx64(t2, 2));                                     \
        ull cIF = padd2(padd2(t0, shx64(t2, 4)), bIF);                    \
        U64F2 uf; uf.u = cIF;                                             \
        float iv = sig_hw(uf.f.x), fv = sig_hw(uf.f.y);                   \
        ull t1 = padd2(P1, shx64(Q1, 1));                                 \
        ull t3 = padd2(P3, shx64(Q3, 1));                                 \
        t1 = padd2(t1, shx64(t1, 2));                                     \
        t3 = padd2(t3, shx64(t3, 2));                                     \
        ull cGO = padd2(padd2(t1, shx64(t3, 4)), bGO);                    \
        uf.u = cGO;                                                       \
        float gg = uf.f.x, go = uf.f.y;                                   \
        const int rw = (RBE) + rlo;                                       \
        if (!dec) {                                                       \
            if (ENCL) {                                                   \
                float gv = tanh_hw(gg), ov = sig_hw(go);                  \
                CST = fv * CST + iv * gv;                                 \
                float hv = ov * tanh_hw(CST);                             \
                if (lead) {                                               \
                    sm[OFF_XHE(WBUF) + rw * XHP + FDIM + U] = hv;         \
                    sm[OFF_XHD(WBUF) + rw * XHP + U]        = hv;         \
                }                                                         \
            }                                                             \
        } else {                                                          \
            if (DECL) {                                                   \
                float gv = tanh_hw(gg), ov = sig_hw(go);                  \
                CST = fv * CST + iv * gv;                                 \
                float hv = ov * tanh_hw(CST);                             \
                if (lead) {                                               \
                    sm[OFF_XHD(WBUF) + rw * XHP + HDIM + U] = hv;         \
                    *(OUTP) = hv;                                         \
                    OUTP += FDIM;                                         \
                }                                                         \
            }                                                             \
            if (lead) {                                                   \
                if (XWC) sm[OFF_XHE(WBUF) + rw * XHP + U] = XPR;          \
                if (XLC) { XPR = *(XLP); XLP += FDIM; }                   \
            }                                                             \
        }                                                                 \
    }

    // ================= pipeline =================
    // A(0): FMA rows01(0) -> bank A  (reads buffer 0)
    FMA8(0, 0, pA0,pA1,pA2,pA3, qA0,qA1,qA2,qA3)
    __syncthreads();
    // B(0): FMA rows23(0) -> bank B; EW(0, rows01) enc-only -> wb=1
    FMA8(0, 2 * XHP, pB0,pB1,pB2,pB3, qB0,qB1,qB2,qB3)
    RED_EW(pA0,pA1,pA2,pA3, qA0,qA1,qA2,qA3, 0, c_lo, true, false, 1,
           outp_lo, x_lo, xl_lo, true, true)
    __syncthreads();
    // A(1): FMA rows01(1) (reads buffer 1); EW(0, rows23) enc-only -> wb=1
    FMA8(1, 0, pA0,pA1,pA2,pA3, qA0,qA1,qA2,qA3)
    RED_EW(pB0,pB1,pB2,pB3, qB0,qB1,qB2,qB3, 2, c_hi, true, false, 1,
           outp_hi, x_hi, xl_hi, true, true)
    __syncthreads();

    #pragma unroll 1
    for (int it = 1; it < T_STEPS; ++it) {
        const int rb = it & 1, wb = rb ^ 1;
        const bool xw = (it + 1 < T_STEPS);
        const bool xl = (it + 2 < T_STEPS);
        // B(it): FMA rows23(it) -> bank B; EW(it, rows01) -> wb
        FMA8(rb, 2 * XHP, pB0,pB1,pB2,pB3, qB0,qB1,qB2,qB3)
        RED_EW(pA0,pA1,pA2,pA3, qA0,qA1,qA2,qA3, 0, c_lo, true, true, wb,
               outp_lo, x_lo, xl_lo, xw, xl)
        __syncthreads();
        // A(it+1): FMA rows01(it+1) (reads wb); EW(it, rows23) -> wb
        FMA8(wb, 0, pA0,pA1,pA2,pA3, qA0,qA1,qA2,qA3)
        RED_EW(pB0,pB1,pB2,pB3, qB0,qB1,qB2,qB3, 2, c_hi, true, true, wb,
               outp_hi, x_hi, xl_hi, xw, xl)
        __syncthreads();
    }

    // B(1024): FMA rows23(1024) (rb=0, valid buffer); EW(1024, rows01) dec-only
    FMA8(0, 2 * XHP, pB0,pB1,pB2,pB3, qB0,qB1,qB2,qB3)
    RED_EW(pA0,pA1,pA2,pA3, qA0,qA1,qA2,qA3, 0, c_lo, false, true, 1,
           outp_lo, x_lo, xl_lo, false, false)
    __syncthreads();
    // final: EW(1024, rows23) dec-only
    RED_EW(pB0,pB1,pB2,pB3, qB0,qB1,qB2,qB3, 2, c_hi, false, true, 1,
           outp_hi, x_hi, xl_hi, false, false)

    #undef RED_EW
    #undef FMA8
    #undef SLOT
    #undef KS
}

extern "C" void kernel_launch(void* const* d_in, const int* in_sizes, int n_in,
                              void* d_out, int out_size)
{
    (void)in_sizes; (void)n_in; (void)out_size;
    lstm_ae_kernel<<<NBLK, NTHR>>>(
        (const float*)d_in[0],
        (const float*)d_in[1], (const float*)d_in[2],
        (const float*)d_in[3], (const float*)d_in[4],
        (const float*)d_in[5], (const float*)d_in[6],
        (const float*)d_in[7], (const float*)d_in[8],
        (float*)d_out);
}

// round 17
// speedup vs baseline: 1.1685x; 1.1685x over previous
#include <cuda_runtime.h>

// LSTM autoencoder: enc (F=32 -> H=64), dec (H=64 -> F=32), B=512, T=1024.
// 128 blocks x 384 threads, 4 batch rows/block.
// ENC/DEC SEGMENT INTERLEAVE: per step t, two block-barrier segments with
// complementary roles so every tail issues under the other group's FMA:
//   seg1: enc = reduce/ew(t)      | dec = FMA_dec(t-1)   (full 192 ffma2)
//   seg2: enc = FMA_enc(t+1)      | dec = reduce/ew(t-1) + x-pipeline
// Buffer parities: FMA_enc(t+1) and FMA_dec(t-1) both read parity pe=(t+1)&1;
// ew stores h into xhD[pd=t&1] (and xhE[pe] h-half for enc); x(t+2)->xhE[pd].
// Every producer->consumer pair is barrier-separated; concurrent seg accesses
// hit disjoint buffers.
// Compute core = R14 (best known): tid = pg*8+s, weights gate-pair packed
// (c0/c1 = MY unit IF/GO, c2/c3 = partner), hv fed as pk(F,F) from 3 LDS.128
// per slot, slot l = row (s^l)&3, xor1 merged inside the FMA part (8 live
// accs), xor2+xor4 select-free exchange + HW-tanh activations in the ew part.
// Biases folded into lane-0 accumulator init. XHP=104 -> conflict-free LDS.

#define T_STEPS 1024
#define FDIM    32
#define HDIM    64
#define ROWS    4
#define NBLK    128
#define NTHR    384
#define XHP     104

#define SEG     (ROWS * XHP)
// xhE buffers at 0, SEG; xhD buffers at 2*SEG, 3*SEG
#define SMEMN   (4 * SEG)

typedef unsigned long long ull;
union U64F2 { ull u; float2 f; };

__device__ __forceinline__ ull pk(float lo, float hi) {
    U64F2 u; u.f = make_float2(lo, hi); return u.u;
}
__device__ __forceinline__ ull ffma2(ull a, ull b, ull c) {
    ull d;
    asm("fma.rn.f32x2 %0, %1, %2, %3;" : "=l"(d) : "l"(a), "l"(b), "l"(c));
    return d;
}
__device__ __forceinline__ ull padd2(ull a, ull b) {
    ull d;
    asm("add.rn.f32x2 %0, %1, %2;" : "=l"(d) : "l"(a), "l"(b));
    return d;
}
__device__ __forceinline__ ull shx64(ull v, int m) {
    return __shfl_xor_sync(0xFFFFFFFFu, v, m);
}
__device__ __forceinline__ float tanh_hw(float x) {
    float r; asm("tanh.approx.f32 %0, %1;" : "=f"(r) : "f"(x)); return r;
}
__device__ __forceinline__ float sig_hw(float g) {   // g pre-scaled by 0.5
    return fmaf(0.5f, tanh_hw(g), 0.5f);
}

__global__ void __launch_bounds__(NTHR, 1) lstm_ae_kernel(
    const float* __restrict__ x,
    const float* __restrict__ ew_ih, const float* __restrict__ ew_hh,
    const float* __restrict__ eb_ih, const float* __restrict__ eb_hh,
    const float* __restrict__ dw_ih, const float* __restrict__ dw_hh,
    const float* __restrict__ db_ih, const float* __restrict__ db_hh,
    float* __restrict__ out)
{
    __shared__ __align__(16) float sm[SMEMN];
    const int tid = threadIdx.x;
    const int b0  = blockIdx.x * ROWS;

    const int pg   = tid >> 3;            // unit-pair 0..47; warps 0-7 enc, 8-11 dec
    const bool dec = (pg >= 32);
    const int pp   = dec ? (pg - 32) : pg;
    const int s    = tid & 7;             // k-eighth lane
    const int uu   = (s >> 2) & 1;
    const int row  = s & 3;               // my elementwise row
    const int kb   = 12 * s;
    const int uA   = 2 * pp;
    const int U    = uA + uu;             // my unit -> chains c0/c1
    const int Uo   = uA + (uu ^ 1);       // partner unit -> chains c2/c3

    // ---- weights: c0/c1 = MY unit (IF)/(GO), c2/c3 = partner; 0.5 on i,f,o ----
    ull w0[12], w1[12], w2[12], w3[12];
    {
        const int NU = dec ? FDIM : HDIM;
        const int KI = dec ? HDIM : FDIM;
        const int KH = dec ? FDIM : HDIM;
        const float* wih = dec ? dw_ih : ew_ih;
        const float* whh = dec ? dw_hh : ew_hh;
        #define WV(G, K) ((K) < KI ? wih[(G) * KI + (K)] : whh[(G) * KH + ((K) - KI)])
        #pragma unroll
        for (int j = 0; j < 12; ++j) {
            const int k = kb + j;
            w0[j] = pk(0.5f * WV(U, k),        0.5f * WV(U + NU, k));
            w1[j] = pk(WV(U + 2 * NU, k),      0.5f * WV(U + 3 * NU, k));
            w2[j] = pk(0.5f * WV(Uo, k),       0.5f * WV(Uo + NU, k));
            w3[j] = pk(WV(Uo + 2 * NU, k),     0.5f * WV(Uo + 3 * NU, k));
        }
        #undef WV
    }

    // ---- packed pre-scaled biases, carried only on lane s==0 (uu=0) ----
    ull bIFa = 0ull, bGOa = 0ull, bIFb = 0ull, bGOb = 0ull;
    {
        const int NU = dec ? FDIM : HDIM;
        const float* bih = dec ? db_ih : eb_ih;
        const float* bhh = dec ? db_hh : eb_hh;
        if (s == 0) {   // lane 0: chains c0/c1 = unit uA, c2/c3 = uA+1
            #define BV(G) (bih[G] + bhh[G])
            bIFa = pk(0.5f * BV(uA),            0.5f * BV(uA + NU));
            bGOa = pk(BV(uA + 2 * NU),          0.5f * BV(uA + 3 * NU));
            bIFb = pk(0.5f * BV(uA + 1),        0.5f * BV(uA + 1 + NU));
            bGOb = pk(BV(uA + 1 + 2 * NU),      0.5f * BV(uA + 1 + 3 * NU));
            #undef BV
        }
    }

    // ---- init: zero state; x(0)->xhE[0], x(1)->xhE[1], x_pref = x(2) ----
    for (int i = tid; i < SMEMN; i += NTHR) sm[i] = 0.0f;
    __syncthreads();
    const float* xrow = x + ((size_t)(b0 + row) * T_STEPS) * FDIM + U;
    float* outp = out + ((size_t)(b0 + row) * T_STEPS) * FDIM + U;   // dec only
    const float* xl = xrow + 3 * FDIM;   // next LDG target: x(3)
    float x_pref = 0.0f;
    if (dec) {
        sm[0 * SEG + row * XHP + U] = xrow[0];       // x(0) -> xhE[0]
        sm[1 * SEG + row * XHP + U] = xrow[FDIM];    // x(1) -> xhE[1]
        x_pref = xrow[2 * FDIM];                     // x(2)
    }
    __syncthreads();

    // row offsets in permuted slot order (s^l)&3
    const int ro0 = ((s)     & 3) * XHP;
    const int ro1 = ((s ^ 1) & 3) * XHP;
    const int ro2 = ((s ^ 2) & 3) * XHP;
    const int ro3 = ((s ^ 3) & 3) * XHP;

    const float* xbase = sm + (dec ? 2 * SEG : 0);   // my lstm's buffer pair

    float c_st = 0.0f;
    // live accumulators (xor1-merged): a* = slots01, bb* = slots23
    ull a0, a1, a2, a3, bb0, bb1, bb2, bb3;

    #define KS(J, F)                                                      \
    {                                                                     \
        ull hd = pk(F, F);                                                \
        c0 = ffma2(w0[J], hd, c0); c1 = ffma2(w1[J], hd, c1);             \
        c2 = ffma2(w2[J], hd, c2); c3 = ffma2(w3[J], hd, c3);             \
    }
    #define DO_ROW(XH, RO, O0, O1, O2, O3)                                \
    {                                                                     \
        const float4* hp = reinterpret_cast<const float4*>((XH) + (RO));  \
        float4 v0 = hp[0], v1 = hp[1], v2 = hp[2];                        \
        ull c0 = bIFa, c1 = bGOa, c2 = bIFb, c3 = bGOb;                   \
        KS(0, v0.x) KS(1, v0.y) KS(2, v0.z) KS(3, v0.w)                   \
        KS(4, v1.x) KS(5, v1.y) KS(6, v1.z) KS(7, v1.w)                   \
        KS(8, v2.x) KS(9, v2.y) KS(10, v2.z) KS(11, v2.w)                 \
        O0 = c0; O1 = c1; O2 = c2; O3 = c3;                               \
    }
    // full 4-slot FMA + xor1 merges -> a*, bb*
    #define FMA_PART(PBUF)                                                \
    {                                                                     \
        const float* xh = xbase + (PBUF) * SEG + kb;                      \
        ull p0, p1, p2, p3, q0, q1, q2, q3;                               \
        DO_ROW(xh, ro0, p0, p1, p2, p3)                                   \
        DO_ROW(xh, ro1, q0, q1, q2, q3)                                   \
        a0 = padd2(p0, shx64(q0, 1));                                     \
        a1 = padd2(p1, shx64(q1, 1));                                     \
        a2 = padd2(p2, shx64(q2, 1));                                     \
        a3 = padd2(p3, shx64(q3, 1));                                     \
        DO_ROW(xh, ro2, p0, p1, p2, p3)                                   \
        DO_ROW(xh, ro3, q0, q1, q2, q3)                                   \
        bb0 = padd2(p0, shx64(q0, 1));                                    \
        bb1 = padd2(p1, shx64(q1, 1));                                    \
        bb2 = padd2(p2, shx64(q2, 1));                                    \
        bb3 = padd2(p3, shx64(q3, 1));                                    \
    }
    // xor2 + xor4 exchange + activations; produces hv
    #define EW_GATES(HV)                                                  \
        float HV;                                                         \
        {                                                                 \
            ull t0 = padd2(a0, shx64(bb0, 2));                            \
            ull t2 = padd2(a2, shx64(bb2, 2));                            \
            ull cIF = padd2(t0, shx64(t2, 4));                            \
            U64F2 uf; uf.u = cIF;                                         \
            float iv = sig_hw(uf.f.x), fv = sig_hw(uf.f.y);               \
            ull t1 = padd2(a1, shx64(bb1, 2));                            \
            ull t3 = padd2(a3, shx64(bb3, 2));                            \
            ull cGO = padd2(t1, shx64(t3, 4));                            \
            uf.u = cGO;                                                   \
            float gv = tanh_hw(uf.f.x);                                   \
            float ov = sig_hw(uf.f.y);                                    \
            c_st = fv * c_st + iv * gv;                                   \
            HV = ov * tanh_hw(c_st);                                      \
        }

    // ---- prologue: enc primes its accumulators with step 0 ----
    if (!dec) FMA_PART(0)
    __syncthreads();

    #pragma unroll 1
    for (int t = 0; t < T_STEPS; ++t) {
        const int pe = (t + 1) & 1;   // read parity for both FMAs
        const int pd = t & 1;         // xhD write parity
        // ===== seg1: enc ew(t)  |  dec FMA(t-1) =====
        if (!dec) {
            EW_GATES(hv)
            sm[pe * SEG + row * XHP + FDIM + U]       = hv;  // xhE[pe] h-half
            sm[(2 + pd) * SEG + row * XHP + U]        = hv;  // xhD[pd] h_enc
        } else if (t > 0) {
            FMA_PART(pe)    // xhD[pe] = (h_enc(t-1), h_dec(t-2))
        }
        __syncthreads();
        // ===== seg2: enc FMA(t+1)  |  dec ew(t-1) + x pipeline =====
        if (!dec) {
            FMA_PART(pe)    // xhE[pe] = (x(t+1), h_enc(t))
        } else {
            if (t > 0) {
                EW_GATES(hv)
                sm[(2 + pd) * SEG + row * XHP + HDIM + U] = hv;  // xhD[pd] h_dec
                *outp = hv;
                outp += FDIM;
            }
            if (t + 2 < T_STEPS)
                sm[pd * SEG + row * XHP + U] = x_pref;           // x(t+2)
            if (t + 3 < T_STEPS) {
                x_pref = *xl;
                xl += FDIM;
            }
        }
        __syncthreads();
    }

    // ---- epilogue: dec step 1023 ----
    if (dec) {
        FMA_PART(1)          // xhD[1] = (h_enc(1023), h_dec(1022))
        EW_GATES(hv)
        *outp = hv;
    }

    #undef EW_GATES
    #undef FMA_PART
    #undef DO_ROW
    #undef KS
}

extern "C" void kernel_launch(void* const* d_in, const int* in_sizes, int n_in,
                              void* d_out, int out_size)
{
    (void)in_sizes; (void)n_in; (void)out_size;
    lstm_ae_kernel<<<NBLK, NTHR>>>(
        (const float*)d_in[0],
        (const float*)d_in[1], (const float*)d_in[2],
        (const float*)d_in[3], (const float*)d_in[4],
        (const float*)d_in[5], (const float*)d_in[6],
        (const float*)d_in[7], (const float*)d_in[8],
        (float*)d_out);
}